// round 2
// baseline (speedup 1.0000x reference)
#include <cuda_runtime.h>

#define Bv 4
#define CIN 256
#define HW 65536
#define Lv 5000
#define DLOI 128
#define DFC 1024
#define NOUT 2500
#define NLINES (Bv*Lv)

// ---------------- scratch (static __device__, no allocs) ----------------
__device__ float g_x[(size_t)Bv * HW * DLOI];     // conv output, pixel-major [b][p][o]
__device__ float g_flat[(size_t)NLINES * DFC];    // pooled features [n][1024]
__device__ float g_h1[(size_t)NLINES * DFC];
__device__ float g_h2[(size_t)NLINES * DFC];
__device__ float g_s[NLINES * 4];                 // softmax scores
__device__ int   g_key[NLINES];                   // mask ? argmax : -1
__device__ int   g_order[NLINES];                 // per-batch counting-sort order

// ---------------- K1: 1x1 conv  x[b][p][o] = sum_c f[b][c][p]*w[o][c] + bias[o]
__global__ __launch_bounds__(256) void conv1x1_kernel(const float* __restrict__ feat,
                                                      const float* __restrict__ w,
                                                      const float* __restrict__ bias) {
    __shared__ float Ws[32][132];   // [c][o], padded: 132*4 % 16 == 0
    __shared__ float Fs[32][68];    // [c][p], padded: 68*4 % 16 == 0
    const int b = blockIdx.y;
    const int p0 = blockIdx.x * 64;
    const int tid = threadIdx.x;
    const int tx = tid & 15, ty = tid >> 4;     // tx -> 4 pixels, ty -> 8 outputs
    const float* fb = feat + (size_t)b * CIN * HW;

    float acc[8][4];
#pragma unroll
    for (int i = 0; i < 8; i++)
#pragma unroll
        for (int j = 0; j < 4; j++) acc[i][j] = 0.f;

    const int wo = tid >> 1;             // 0..127 output row
    const int wslot = (tid & 1) * 4;     // float4 slot within 8 (32 c's)
    const int fc = tid >> 3;             // 0..31 channel row
    const int fp4 = (tid & 7) * 2;       // float4 slot within 16 (64 px)

    for (int c0 = 0; c0 < CIN; c0 += 32) {
        __syncthreads();
#pragma unroll
        for (int i = 0; i < 4; i++) {
            float4 v = *(const float4*)&w[(size_t)wo * CIN + c0 + (wslot + i) * 4];
            Ws[(wslot + i) * 4 + 0][wo] = v.x;
            Ws[(wslot + i) * 4 + 1][wo] = v.y;
            Ws[(wslot + i) * 4 + 2][wo] = v.z;
            Ws[(wslot + i) * 4 + 3][wo] = v.w;
        }
#pragma unroll
        for (int i = 0; i < 2; i++) {
            float4 v = *(const float4*)&fb[(size_t)(c0 + fc) * HW + p0 + (fp4 + i) * 4];
            *(float4*)&Fs[fc][(fp4 + i) * 4] = v;
        }
        __syncthreads();
#pragma unroll
        for (int c = 0; c < 32; c++) {
            float4 a0 = *(const float4*)&Ws[c][ty * 8];
            float4 a1 = *(const float4*)&Ws[c][ty * 8 + 4];
            float4 f0 = *(const float4*)&Fs[c][tx * 4];
            float a[8] = {a0.x, a0.y, a0.z, a0.w, a1.x, a1.y, a1.z, a1.w};
            float f[4] = {f0.x, f0.y, f0.z, f0.w};
#pragma unroll
            for (int i = 0; i < 8; i++)
#pragma unroll
                for (int j = 0; j < 4; j++) acc[i][j] += a[i] * f[j];
        }
    }

    float bs[8];
#pragma unroll
    for (int i = 0; i < 8; i++) bs[i] = bias[ty * 8 + i];
    float* xb = g_x + (size_t)b * HW * DLOI;
#pragma unroll
    for (int j = 0; j < 4; j++) {
        int p = p0 + tx * 4 + j;
        float4 v0 = make_float4(acc[0][j] + bs[0], acc[1][j] + bs[1],
                                acc[2][j] + bs[2], acc[3][j] + bs[3]);
        float4 v1 = make_float4(acc[4][j] + bs[4], acc[5][j] + bs[5],
                                acc[6][j] + bs[6], acc[7][j] + bs[7]);
        *(float4*)&xb[(size_t)p * DLOI + ty * 8] = v0;
        *(float4*)&xb[(size_t)p * DLOI + ty * 8 + 4] = v1;
    }
}

// ---------------- K2: sample 32 pts/line, bilinear, maxpool(4) -> flat[n][c*8+g]
__global__ __launch_bounds__(128) void sample_pool_kernel(const float* __restrict__ lines) {
    const int b = blockIdx.y, l = blockIdx.x, c = threadIdx.x;   // c = channel
    const float* ln = lines + ((size_t)b * Lv + l) * 4;
    const float p0x = ln[0], p0y = ln[1], p1x = ln[2], p1y = ln[3];
    const float* xb = g_x + (size_t)b * HW * DLOI;
    __shared__ float buf[DFC];

    float m = -3.402823466e38f;
#pragma unroll 4
    for (int j = 0; j < 32; j++) {
        float lam = (1.0f / 31.0f) * (float)j;
        float px = p0x * lam + p1x * (1.f - lam) - 0.5f;
        float py = p0y * lam + p1y * (1.f - lam) - 0.5f;
        float px0 = fminf(fmaxf(floorf(px), 0.f), 255.f);
        float py0 = fminf(fmaxf(floorf(py), 0.f), 255.f);
        float px1 = fminf(px0 + 1.f, 255.f);
        float py1 = fminf(py0 + 1.f, 255.f);
        int ix0 = (int)px0, iy0 = (int)py0, ix1 = (int)px1, iy1 = (int)py1;
        float w00 = (px1 - px) * (py1 - py);
        float w10 = (px - px0) * (py1 - py);
        float w01 = (px1 - px) * (py - py0);
        float w11 = (px - px0) * (py - py0);
        const float* q00 = xb + (size_t)(ix0 * 256 + iy0) * DLOI;
        const float* q10 = xb + (size_t)(ix1 * 256 + iy0) * DLOI;
        const float* q01 = xb + (size_t)(ix0 * 256 + iy1) * DLOI;
        const float* q11 = xb + (size_t)(ix1 * 256 + iy1) * DLOI;
        float v = q00[c] * w00 + q10[c] * w10 + q01[c] * w01 + q11[c] * w11;
        m = fmaxf(m, v);
        if ((j & 3) == 3) {
            buf[c * 8 + (j >> 2)] = m;
            m = -3.402823466e38f;
        }
    }
    __syncthreads();
    float* out = g_flat + ((size_t)b * Lv + l) * DFC;
    float4* o4 = (float4*)out;
    const float4* b4 = (const float4*)buf;
    o4[c] = b4[c];
    o4[c + 128] = b4[c + 128];
}

// ---------------- K3/K4: C[n][m] = act( A[n][:] . W[m][:] + bias[m] ), K=M=1024
__global__ __launch_bounds__(256) void gemm_nt_kernel(const float* __restrict__ A,
                                                      const float* __restrict__ W,
                                                      const float* __restrict__ bias,
                                                      float* __restrict__ C,
                                                      int N, int relu) {
    __shared__ float As[16][132];
    __shared__ float Bs[16][132];
    const int tid = threadIdx.x;
    const int tx = tid & 15, ty = tid >> 4;
    const int rowbase = blockIdx.y * 128;
    const int colbase = blockIdx.x * 128;
    const int lr = tid >> 1;
    const int lk = (tid & 1) * 2;

    float acc[8][8];
#pragma unroll
    for (int i = 0; i < 8; i++)
#pragma unroll
        for (int j = 0; j < 8; j++) acc[i][j] = 0.f;

    for (int k0 = 0; k0 < DFC; k0 += 16) {
        __syncthreads();
#pragma unroll
        for (int i = 0; i < 2; i++) {
            int kq = lk + i;
            int row = rowbase + lr;
            float4 v = make_float4(0.f, 0.f, 0.f, 0.f);
            if (row < N) v = *(const float4*)&A[(size_t)row * DFC + k0 + kq * 4];
            As[kq * 4 + 0][lr] = v.x; As[kq * 4 + 1][lr] = v.y;
            As[kq * 4 + 2][lr] = v.z; As[kq * 4 + 3][lr] = v.w;
            float4 u = *(const float4*)&W[(size_t)(colbase + lr) * DFC + k0 + kq * 4];
            Bs[kq * 4 + 0][lr] = u.x; Bs[kq * 4 + 1][lr] = u.y;
            Bs[kq * 4 + 2][lr] = u.z; Bs[kq * 4 + 3][lr] = u.w;
        }
        __syncthreads();
#pragma unroll
        for (int k = 0; k < 16; k++) {
            float4 a0 = *(const float4*)&As[k][ty * 8];
            float4 a1 = *(const float4*)&As[k][ty * 8 + 4];
            float4 b0 = *(const float4*)&Bs[k][tx * 8];
            float4 b1 = *(const float4*)&Bs[k][tx * 8 + 4];
            float a[8] = {a0.x, a0.y, a0.z, a0.w, a1.x, a1.y, a1.z, a1.w};
            float bb[8] = {b0.x, b0.y, b0.z, b0.w, b1.x, b1.y, b1.z, b1.w};
#pragma unroll
            for (int i = 0; i < 8; i++)
#pragma unroll
                for (int j = 0; j < 8; j++) acc[i][j] += a[i] * bb[j];
        }
    }

    float bsv[8];
#pragma unroll
    for (int j = 0; j < 8; j++) bsv[j] = bias[colbase + tx * 8 + j];
#pragma unroll
    for (int i = 0; i < 8; i++) {
        int row = rowbase + ty * 8 + i;
        if (row >= N) continue;
        float r[8];
#pragma unroll
        for (int j = 0; j < 8; j++) {
            float v = acc[i][j] + bsv[j];
            r[j] = relu ? fmaxf(v, 0.f) : v;
        }
        float* cp = &C[(size_t)row * DFC + colbase + tx * 8];
        *(float4*)cp = make_float4(r[0], r[1], r[2], r[3]);
        *(float4*)(cp + 4) = make_float4(r[4], r[5], r[6], r[7]);
    }
}

// ---------------- K5: logits -> softmax -> mask/key (warp per line)
__global__ __launch_bounds__(256) void head_kernel(const float* __restrict__ w3,
                                                   const float* __restrict__ b3) {
    const int line = blockIdx.x * 8 + (threadIdx.x >> 5);
    if (line >= NLINES) return;
    const int lane = threadIdx.x & 31;
    const float4* hr = (const float4*)(g_h2 + (size_t)line * DFC);
    const float4* wr0 = (const float4*)(w3);
    const float4* wr1 = (const float4*)(w3 + DFC);
    const float4* wr2 = (const float4*)(w3 + 2 * DFC);
    const float4* wr3 = (const float4*)(w3 + 3 * DFC);
    float a0 = 0.f, a1 = 0.f, a2 = 0.f, a3 = 0.f;
    for (int k = lane; k < 256; k += 32) {
        float4 h = hr[k];
        float4 x;
        x = wr0[k]; a0 += h.x * x.x + h.y * x.y + h.z * x.z + h.w * x.w;
        x = wr1[k]; a1 += h.x * x.x + h.y * x.y + h.z * x.z + h.w * x.w;
        x = wr2[k]; a2 += h.x * x.x + h.y * x.y + h.z * x.z + h.w * x.w;
        x = wr3[k]; a3 += h.x * x.x + h.y * x.y + h.z * x.z + h.w * x.w;
    }
#pragma unroll
    for (int d = 16; d > 0; d >>= 1) {
        a0 += __shfl_xor_sync(0xffffffffu, a0, d);
        a1 += __shfl_xor_sync(0xffffffffu, a1, d);
        a2 += __shfl_xor_sync(0xffffffffu, a2, d);
        a3 += __shfl_xor_sync(0xffffffffu, a3, d);
    }
    if (lane == 0) {
        float l0 = a0 + b3[0], l1 = a1 + b3[1], l2 = a2 + b3[2], l3 = a3 + b3[3];
        float mx = fmaxf(fmaxf(l0, l1), fmaxf(l2, l3));
        float e0 = expf(l0 - mx), e1 = expf(l1 - mx), e2 = expf(l2 - mx), e3 = expf(l3 - mx);
        float inv = 1.f / (e0 + e1 + e2 + e3);
        float s0 = e0 * inv, s1 = e1 * inv, s2 = e2 * inv, s3 = e3 * inv;
        int am = 0; float bm = l0;
        if (l1 > bm) { am = 1; bm = l1; }
        if (l2 > bm) { am = 2; bm = l2; }
        if (l3 > bm) { am = 3; bm = l3; }
        bool mask = (s1 > 0.25f || s2 > 0.25f || s3 > 0.25f) && (s0 < 0.25f);
        *(float4*)&g_s[line * 4] = make_float4(s0, s1, s2, s3);
        g_key[line] = mask ? am : -1;
    }
}

// ---------------- K6: per-batch stable counting sort + cyclic gather to output
__global__ __launch_bounds__(1024) void select_kernel(const float* __restrict__ lines,
                                                      float* __restrict__ out) {
    const int b = blockIdx.x;
    const int tid = threadIdx.x;
    const int lane = tid & 31, wid = tid >> 5;
    __shared__ int warp_sums[32];
    __shared__ int s_base;
    if (tid == 0) s_base = 0;
    const int* keyb = g_key + b * Lv;
    int* ordb = g_order + b * Lv;

    for (int kv = 3; kv >= 0; kv--) {
        for (int chunk = 0; chunk < Lv; chunk += 1024) {
            __syncthreads();   // protects s_base / warp_sums from prev iteration
            int i = chunk + tid;
            int pred = (i < Lv && keyb[i] == kv) ? 1 : 0;
            int incl = pred;
#pragma unroll
            for (int d = 1; d < 32; d <<= 1) {
                int v = __shfl_up_sync(0xffffffffu, incl, d);
                if (lane >= d) incl += v;
            }
            if (lane == 31) warp_sums[wid] = incl;
            __syncthreads();
            if (wid == 0) {
                int inc2 = warp_sums[lane];
#pragma unroll
                for (int d = 1; d < 32; d <<= 1) {
                    int t = __shfl_up_sync(0xffffffffu, inc2, d);
                    if (lane >= d) inc2 += t;
                }
                warp_sums[lane] = inc2;
            }
            __syncthreads();
            int excl = incl - pred + (wid > 0 ? warp_sums[wid - 1] : 0);
            int total = warp_sums[31];
            int base = s_base;
            if (pred) ordb[base + excl] = i;
            __syncthreads();
            if (tid == 0) s_base = base + total;
        }
    }
    __syncthreads();
    const int cnt = s_base;

    float* out_lines = out + (size_t)b * NOUT * 4;
    float* out_scores = out + (size_t)Bv * NOUT * 4 + (size_t)b * NOUT * 4;
    for (int i = tid; i < NOUT; i += 1024) {
        float4 lv = make_float4(0.f, 0.f, 0.f, 0.f);
        float4 sv = make_float4(0.f, 0.f, 0.f, 0.f);
        if (cnt > 0) {
            int sel = ordb[i % cnt];
            lv = *(const float4*)&lines[((size_t)b * Lv + sel) * 4];
            sv = *(const float4*)&g_s[(b * Lv + sel) * 4];
        }
        *(float4*)&out_lines[(size_t)i * 4] = lv;
        *(float4*)&out_scores[(size_t)i * 4] = sv;
    }
}

// ---------------- launch ----------------
extern "C" void kernel_launch(void* const* d_in, const int* in_sizes, int n_in,
                              void* d_out, int out_size) {
    const float* feature = (const float*)d_in[0];
    const float* lines   = (const float*)d_in[1];
    const float* fc1_w   = (const float*)d_in[2];
    const float* fc1_b   = (const float*)d_in[3];
    const float* w1      = (const float*)d_in[4];
    const float* b1      = (const float*)d_in[5];
    const float* w2      = (const float*)d_in[6];
    const float* b2      = (const float*)d_in[7];
    const float* w3      = (const float*)d_in[8];
    const float* b3      = (const float*)d_in[9];
    float* out = (float*)d_out;

    void *p_flat, *p_h1, *p_h2;
    cudaGetSymbolAddress(&p_flat, g_flat);
    cudaGetSymbolAddress(&p_h1, g_h1);
    cudaGetSymbolAddress(&p_h2, g_h2);

    conv1x1_kernel<<<dim3(HW / 64, Bv), 256>>>(feature, fc1_w, fc1_b);
    sample_pool_kernel<<<dim3(Lv, Bv), 128>>>(lines);
    gemm_nt_kernel<<<dim3(DFC / 128, (NLINES + 127) / 128), 256>>>(
        (const float*)p_flat, w1, b1, (float*)p_h1, NLINES, 1);
    gemm_nt_kernel<<<dim3(DFC / 128, (NLINES + 127) / 128), 256>>>(
        (const float*)p_h1, w2, b2, (float*)p_h2, NLINES, 1);
    head_kernel<<<(NLINES + 7) / 8, 256>>>(w3, b3);
    select_kernel<<<Bv, 1024>>>(lines, out);
}